// round 1
// baseline (speedup 1.0000x reference)
#include <cuda_runtime.h>
#include <cuda_bf16.h>

#define NN 100000
#define EE 3200000
#define MM 1066666
#define GG 1024
#define HID 32

// ---------------- scratch (device globals; allocation-free) ----------------
__device__ float d_sp[4];          // softmax of msg_weights
__device__ float d_Wc[14 * 32];    // folded input->hidden weight
__device__ float d_bc[32];         // folded bias (emb_b @ gcn_W[:52])
__device__ float d_ew[EE];         // per-edge weights
__device__ float d_deg[NN];        // degree, then overwritten with rsqrt(deg)
__device__ float d_hw[NN * HID];   // x @ Wc + bc
__device__ float d_acc[NN * HID];  // aggregation accumulator
__device__ float d_g[GG * HID];    // pooled graph features

__device__ __forceinline__ float gelu_exact(float x) {
    return 0.5f * x * (1.0f + erff(x * 0.70710678118654752f));
}

__device__ __forceinline__ void red_add_f32(float* p, float v) {
    asm volatile("red.global.add.f32 [%0], %1;" :: "l"(p), "f"(v) : "memory");
}

__device__ __forceinline__ void red_add_v4(float4* p, float4 v) {
    asm volatile("red.global.add.v4.f32 [%0], {%1,%2,%3,%4};"
                 :: "l"(p), "f"(v.x), "f"(v.y), "f"(v.z), "f"(v.w) : "memory");
}

// ---------------- k1: softmax + weight folding (1 block, 32 threads) -------
__global__ void k_prep(const float* __restrict__ msg_w,
                       const float* __restrict__ emb_W,
                       const float* __restrict__ emb_b,
                       const float* __restrict__ gcn_W) {
    int j = threadIdx.x;
    if (j == 0) {
        float m = fmaxf(msg_w[0], fmaxf(msg_w[1], msg_w[2]));
        float e0 = expf(msg_w[0] - m);
        float e1 = expf(msg_w[1] - m);
        float e2 = expf(msg_w[2] - m);
        float inv = 1.0f / (e0 + e1 + e2);
        d_sp[0] = e0 * inv; d_sp[1] = e1 * inv; d_sp[2] = e2 * inv;
    }
    if (j < 32) {
        float a0 = 0.f, a1 = 0.f, ab = 0.f;
        #pragma unroll
        for (int k = 0; k < 52; k++) {
            float gw = gcn_W[k * 32 + j];
            a0 += emb_W[k] * gw;        // emb_W row 0
            a1 += emb_W[52 + k] * gw;   // emb_W row 1
            ab += emb_b[k] * gw;
        }
        d_Wc[0 * 32 + j] = a0;
        d_Wc[1 * 32 + j] = a1;
        d_bc[j] = ab;
        #pragma unroll
        for (int f = 0; f < 12; f++)
            d_Wc[(2 + f) * 32 + j] = gcn_W[(52 + f) * 32 + j];
    }
}

// ---------------- k2: fills (ew=1, deg=1 self-loop, g=0) -------------------
__global__ void k_fill() {
    int i = blockIdx.x * blockDim.x + threadIdx.x;   // grid covers EE/4
    float4 one4 = make_float4(1.f, 1.f, 1.f, 1.f);
    float4 z4   = make_float4(0.f, 0.f, 0.f, 0.f);
    if (i < EE / 4) reinterpret_cast<float4*>(d_ew)[i] = one4;
    if (i < NN)     d_deg[i] = 1.0f;                 // self-loop contribution
    if (i < (GG * HID) / 4) reinterpret_cast<float4*>(d_g)[i] = z4;
}

// ---------------- k3-5: ordered mask scatters ------------------------------
__global__ void k_scatter(const int* __restrict__ idx, int which) {
    int i = blockIdx.x * blockDim.x + threadIdx.x;
    if (i < MM) d_ew[idx[i]] = d_sp[which];
}

// ---------------- k6: degree accumulation ----------------------------------
__global__ void k_deg(const int* __restrict__ ei) {
    int e = blockIdx.x * blockDim.x + threadIdx.x;
    if (e < EE) red_add_f32(&d_deg[ei[EE + e]], d_ew[e]);
}

// ---------------- k7: per-node hw, dis, self-loop init ---------------------
__global__ void k_node(const float* __restrict__ x) {
    __shared__ float sW[14 * 32];
    __shared__ float sb[32];
    int tid = threadIdx.x;
    for (int i = tid; i < 14 * 32; i += blockDim.x) sW[i] = d_Wc[i];
    if (tid < 32) sb[tid] = d_bc[tid];
    __syncthreads();

    int n = blockIdx.x * blockDim.x + tid;
    if (n >= NN) return;

    float xv[14];
    #pragma unroll
    for (int k = 0; k < 14; k++) xv[k] = x[n * 14 + k];

    float dis = rsqrtf(d_deg[n]);
    d_deg[n] = dis;              // overwrite deg with rsqrt(deg)
    float dis2 = dis * dis;

    float4* hwp  = reinterpret_cast<float4*>(d_hw)  + n * 8;
    float4* accp = reinterpret_cast<float4*>(d_acc) + n * 8;

    #pragma unroll
    for (int q = 0; q < 8; q++) {
        float4 o;
        float* op = &o.x;
        #pragma unroll
        for (int s = 0; s < 4; s++) {
            int j = q * 4 + s;
            float acc = sb[j];
            #pragma unroll
            for (int k = 0; k < 14; k++) acc += xv[k] * sW[k * 32 + j];
            op[s] = acc;
        }
        hwp[q] = o;
        o.x *= dis2; o.y *= dis2; o.z *= dis2; o.w *= dis2;
        accp[q] = o;             // self-loop: hw[i] * dis[i]^2
    }
}

// ---------------- k8: edge aggregation (8 lanes/edge) ----------------------
__global__ void k_edge(const int* __restrict__ ei) {
    unsigned t = blockIdx.x * blockDim.x + threadIdx.x;  // EE*8 threads exactly
    unsigned e = t >> 3;
    unsigned lane = t & 7;
    int r = 0, c = 0;
    float w = 0.f;
    if (lane == 0) {
        r = ei[e];
        c = ei[EE + e];
        w = d_ew[e] * d_deg[r] * d_deg[c];   // d_deg holds rsqrt(deg)
    }
    r = __shfl_sync(0xFFFFFFFFu, r, 0, 8);
    c = __shfl_sync(0xFFFFFFFFu, c, 0, 8);
    w = __shfl_sync(0xFFFFFFFFu, w, 0, 8);

    float4 v = reinterpret_cast<const float4*>(d_hw)[r * 8 + lane];
    v.x *= w; v.y *= w; v.z *= w; v.w *= w;
    red_add_v4(reinterpret_cast<float4*>(d_acc) + c * 8 + lane, v);
}

// ---------------- k9: gelu + global_add_pool -------------------------------
__global__ void k_pool(const int* __restrict__ batch,
                       const float* __restrict__ gcn_b) {
    unsigned t = blockIdx.x * blockDim.x + threadIdx.x;  // NN*8 threads exactly
    unsigned n = t >> 3;
    unsigned lane = t & 7;
    int b = 0;
    if (lane == 0) b = batch[n];
    b = __shfl_sync(0xFFFFFFFFu, b, 0, 8);

    float4 v  = reinterpret_cast<const float4*>(d_acc)[n * 8 + lane];
    float4 bb = reinterpret_cast<const float4*>(gcn_b)[lane];
    v.x = gelu_exact(v.x + bb.x);
    v.y = gelu_exact(v.y + bb.y);
    v.z = gelu_exact(v.z + bb.z);
    v.w = gelu_exact(v.w + bb.w);
    red_add_v4(reinterpret_cast<float4*>(d_g) + b * 8 + lane, v);
}

// ---------------- k10: backbone MLP ----------------------------------------
__global__ void k_mlp(const float* __restrict__ fc1_W,
                      const float* __restrict__ fc1_b,
                      const float* __restrict__ fc2_W,
                      const float* __restrict__ fc2_b,
                      float* __restrict__ out) {
    __shared__ float sW1[32 * 32];
    __shared__ float sb1[32];
    __shared__ float sW2[32];
    int tid = threadIdx.x;
    for (int i = tid; i < 1024; i += blockDim.x) sW1[i] = fc1_W[i];
    if (tid < 32) { sb1[tid] = fc1_b[tid]; sW2[tid] = fc2_W[tid]; }
    __syncthreads();

    int g = blockIdx.x * blockDim.x + tid;
    if (g >= GG) return;

    float gv[32];
    #pragma unroll
    for (int k = 0; k < 32; k++) gv[k] = d_g[g * 32 + k];

    float acc = fc2_b[0];
    #pragma unroll
    for (int j = 0; j < 32; j++) {
        float s = sb1[j];
        #pragma unroll
        for (int k = 0; k < 32; k++) s += gv[k] * sW1[k * 32 + j];
        acc += gelu_exact(s) * sW2[j];
    }
    out[g] = acc;
}

// ---------------- launch ----------------------------------------------------
extern "C" void kernel_launch(void* const* d_in, const int* in_sizes, int n_in,
                              void* d_out, int out_size) {
    const float* x        = (const float*)d_in[0];
    const int*   ei       = (const int*)  d_in[1];
    const int*   batch    = (const int*)  d_in[2];
    const int*   known    = (const int*)  d_in[3];
    const int*   unk      = (const int*)  d_in[4];
    const int*   obs      = (const int*)  d_in[5];
    const float* msg_w    = (const float*)d_in[6];
    const float* emb_W    = (const float*)d_in[7];
    const float* emb_b    = (const float*)d_in[8];
    const float* gcn_W    = (const float*)d_in[9];
    const float* gcn_b    = (const float*)d_in[10];
    const float* fc1_W    = (const float*)d_in[11];
    const float* fc1_b    = (const float*)d_in[12];
    const float* fc2_W    = (const float*)d_in[13];
    const float* fc2_b    = (const float*)d_in[14];
    float* out = (float*)d_out;

    k_prep<<<1, 32>>>(msg_w, emb_W, emb_b, gcn_W);
    k_fill<<<(EE / 4 + 255) / 256, 256>>>();
    k_scatter<<<(MM + 255) / 256, 256>>>(known, 0);
    k_scatter<<<(MM + 255) / 256, 256>>>(unk, 1);
    k_scatter<<<(MM + 255) / 256, 256>>>(obs, 2);
    k_deg<<<(EE + 255) / 256, 256>>>(ei);
    k_node<<<(NN + 255) / 256, 256>>>(x);
    k_edge<<<(EE * 8) / 256, 256>>>(ei);          // 100000 blocks, exact
    k_pool<<<(NN * 8) / 256, 256>>>(batch, gcn_b); // 3125 blocks, exact
    k_mlp<<<(GG + 255) / 256, 256>>>(fc1_W, fc1_b, fc2_W, fc2_b, out);
}